// round 1
// baseline (speedup 1.0000x reference)
#include <cuda_runtime.h>

#define NN   4096
#define DIN  512
#define HID  256
#define DBOX 22

// ---- scratch (device globals; no allocation allowed) ----
__device__ float g_K[2][NN * HID];
__device__ float g_Q[2][NN * HID];
__device__ float g_V[2][NN * HID];
__device__ float g_M[2][DBOX * DBOX];
__device__ float g_BM[2][NN * DBOX];
__device__ float g_O[2][NN * HID];
__device__ float g_part[2][64];
__device__ float g_isum[2];

// ================= projection GEMM: C[4096,256] = A[4096,512] @ W[512,256] ==========
__global__ __launch_bounds__(256) void proj_kernel(const float* __restrict__ A,
                                                   const float* __restrict__ W,
                                                   int which, int branch) {
    float* C = (which == 0) ? g_K[branch] : (which == 1 ? g_Q[branch] : g_V[branch]);
    __shared__ __align__(16) float As[16][68];
    __shared__ __align__(16) float Ws[16][68];
    const int t = threadIdx.x;
    const int tx = t & 15, ty = t >> 4;
    const int r0 = blockIdx.y * 64;
    const int c0 = blockIdx.x * 64;
    float acc[4][4] = {};
    for (int k0 = 0; k0 < DIN; k0 += 16) {
#pragma unroll
        for (int l = 0; l < 4; ++l) {
            int e = t + l * 256;
            As[e & 15][e >> 4] = A[(r0 + (e >> 4)) * DIN + k0 + (e & 15)];
        }
#pragma unroll
        for (int l = 0; l < 4; ++l) {
            int e = t + l * 256;
            Ws[e >> 6][e & 63] = W[(k0 + (e >> 6)) * HID + c0 + (e & 63)];
        }
        __syncthreads();
#pragma unroll
        for (int kk = 0; kk < 16; ++kk) {
            float4 a4 = *(const float4*)&As[kk][ty * 4];
            float4 w4 = *(const float4*)&Ws[kk][tx * 4];
            float av[4] = {a4.x, a4.y, a4.z, a4.w};
            float wv[4] = {w4.x, w4.y, w4.z, w4.w};
#pragma unroll
            for (int mi = 0; mi < 4; ++mi)
#pragma unroll
                for (int ni = 0; ni < 4; ++ni) acc[mi][ni] += av[mi] * wv[ni];
        }
        __syncthreads();
    }
#pragma unroll
    for (int mi = 0; mi < 4; ++mi) {
        float4 v = make_float4(acc[mi][0], acc[mi][1], acc[mi][2], acc[mi][3]);
        *(float4*)&C[(r0 + ty * 4 + mi) * HID + c0 + tx * 4] = v;
    }
}

// ================= M = WG @ WG^T  (22x22, inner 256) ==============================
__global__ void gramm_kernel(const float* __restrict__ WG1, const float* __restrict__ WG2) {
    const float* WG = blockIdx.x ? WG2 : WG1;
    int t = threadIdx.x;
    if (t < DBOX * DBOX) {
        int i = t / DBOX, j = t % DBOX;
        float s = 0.f;
        for (int d = 0; d < HID; ++d) s += WG[i * HID + d] * WG[j * HID + d];
        g_M[blockIdx.x][t] = s;
    }
}

// ================= BM = box @ M   [4096, 22] ======================================
__global__ __launch_bounds__(256) void bm_kernel(const float* __restrict__ box) {
    __shared__ float Ms[DBOX * DBOX];
    int b = blockIdx.y, t = threadIdx.x;
    for (int i = t; i < DBOX * DBOX; i += 256) Ms[i] = g_M[b][i];
    __syncthreads();
    int e = blockIdx.x * 256 + t;  // grid.x = 352 -> exactly 4096*22
    int r = e / DBOX, c = e % DBOX;
    float s = 0.f;
#pragma unroll
    for (int k = 0; k < DBOX; ++k) s += box[r * DBOX + k] * Ms[k * DBOX + c];
    g_BM[b][e] = s;
}

// ================= fused attention: O = S @ V, partial sums =======================
// S_ij = relu((BM_i . box_j)/16) * exp((K_i . Q_j)/16), never materialized globally.
__global__ __launch_bounds__(256, 1) void attn_kernel(const float* __restrict__ box) {
    const int b = blockIdx.y;
    const int i0 = blockIdx.x * 64;
    const float* __restrict__ K = g_K[b];
    const float* __restrict__ Q = g_Q[b];
    const float* __restrict__ V = g_V[b];

    __shared__ __align__(16) float sBM[64][23];
    __shared__ __align__(16) float sBox[64][23];
    __shared__ __align__(16) float sKQ[2][32][68];   // stage A chunks; aliased as S[64][68]
    __shared__ __align__(16) float sV[16][256];
    __shared__ float sred[256];
    float (*sS)[68] = reinterpret_cast<float(*)[68]>(&sKQ[0][0][0]);

    const int t = threadIdx.x;
    const int tx = t & 15, ty = t >> 4;   // stage A: 16x16 threads, 4x4 micro
    const int cg = t & 31, rg = t >> 5;   // stage B: 8x32 threads, 8x8 micro

    for (int e = t; e < 64 * DBOX; e += 256)
        sBM[e / DBOX][e % DBOX] = g_BM[b][(i0 + e / DBOX) * DBOX + e % DBOX];

    float acc[8][8] = {};
    float sumLoc = 0.f;

#pragma unroll 1
    for (int j0 = 0; j0 < NN; j0 += 64) {
        float a[4][4] = {};
        float g[4][4] = {};
        for (int e = t; e < 64 * DBOX; e += 256)
            sBox[e / DBOX][e % DBOX] = box[(j0 + e / DBOX) * DBOX + e % DBOX];

        // ---- stage A: a = K_i . Q_j over d=0..255 in 32-wide chunks ----
#pragma unroll 1
        for (int d0 = 0; d0 < HID; d0 += 32) {
            __syncthreads();   // prior readers of sKQ/sS done before overwrite
#pragma unroll
            for (int l = 0; l < 8; ++l) {
                int e = t + l * 256;
                int dd = e & 31, r = e >> 5;
                sKQ[0][dd][r] = K[(i0 + r) * HID + d0 + dd];
                sKQ[1][dd][r] = Q[(j0 + r) * HID + d0 + dd];
            }
            __syncthreads();
#pragma unroll
            for (int kk = 0; kk < 32; ++kk) {
                float4 k4 = *(const float4*)&sKQ[0][kk][ty * 4];
                float4 q4 = *(const float4*)&sKQ[1][kk][tx * 4];
                float kv[4] = {k4.x, k4.y, k4.z, k4.w};
                float qv[4] = {q4.x, q4.y, q4.z, q4.w};
#pragma unroll
                for (int mi = 0; mi < 4; ++mi)
#pragma unroll
                    for (int ni = 0; ni < 4; ++ni) a[mi][ni] += kv[mi] * qv[ni];
            }
        }
        __syncthreads();

        // ---- gate gram via rank-22 trick: g = BM_i . box_j ----
#pragma unroll
        for (int dd = 0; dd < DBOX; ++dd) {
            float bmv[4], bxv[4];
#pragma unroll
            for (int mi = 0; mi < 4; ++mi) bmv[mi] = sBM[ty * 4 + mi][dd];
#pragma unroll
            for (int ni = 0; ni < 4; ++ni) bxv[ni] = sBox[tx * 4 + ni][dd];
#pragma unroll
            for (int mi = 0; mi < 4; ++mi)
#pragma unroll
                for (int ni = 0; ni < 4; ++ni) g[mi][ni] += bmv[mi] * bxv[ni];
        }

        // ---- combine: s = relu(g/16) * exp(a/16); store S tile, track sum ----
#pragma unroll
        for (int mi = 0; mi < 4; ++mi)
#pragma unroll
            for (int ni = 0; ni < 4; ++ni) {
                float gv = g[mi][ni];
                float s = (gv > 0.f) ? gv * 0.0625f * __expf(a[mi][ni] * 0.0625f) : 0.f;
                sumLoc += s;
                sS[ty * 4 + mi][tx * 4 + ni] = s;
            }
        __syncthreads();

        // ---- stage B: O[64x256] += S[64x64] @ V_j[64x256], V streamed 16 rows at a time ----
#pragma unroll 1
        for (int jc = 0; jc < 4; ++jc) {
#pragma unroll
            for (int l = 0; l < 4; ++l) {
                int idx = t + l * 256;          // float4 index over 16x64
                int rr = idx >> 6, c4 = idx & 63;
                *(float4*)&sV[rr][c4 * 4] =
                    *(const float4*)&V[(j0 + jc * 16 + rr) * HID + c4 * 4];
            }
            __syncthreads();
#pragma unroll
            for (int uu = 0; uu < 16; ++uu) {
                float sv[8];
#pragma unroll
                for (int i = 0; i < 8; ++i) sv[i] = sS[rg * 8 + i][jc * 16 + uu];  // broadcast
                float4 v0 = *(const float4*)&sV[uu][cg * 8];
                float4 v1 = *(const float4*)&sV[uu][cg * 8 + 4];
                float vv[8] = {v0.x, v0.y, v0.z, v0.w, v1.x, v1.y, v1.z, v1.w};
#pragma unroll
                for (int i = 0; i < 8; ++i)
#pragma unroll
                    for (int k = 0; k < 8; ++k) acc[i][k] += sv[i] * vv[k];
            }
            __syncthreads();
        }
    }

    // ---- write unnormalized O strip ----
#pragma unroll
    for (int i = 0; i < 8; ++i) {
        int row = i0 + rg * 8 + i;
        *(float4*)&g_O[b][row * HID + cg * 8] =
            make_float4(acc[i][0], acc[i][1], acc[i][2], acc[i][3]);
        *(float4*)&g_O[b][row * HID + cg * 8 + 4] =
            make_float4(acc[i][4], acc[i][5], acc[i][6], acc[i][7]);
    }

    // ---- deterministic partial-sum (no float atomics) ----
    sred[t] = sumLoc;
    __syncthreads();
    for (int s2 = 128; s2 > 0; s2 >>= 1) {
        if (t < s2) sred[t] += sred[t + s2];
        __syncthreads();
    }
    if (t == 0) g_part[b][blockIdx.x] = sred[0];
}

// ================= deterministic final sum -> 0.1 / sum ===========================
__global__ void sum_kernel() {
    if (threadIdx.x == 0) {
        float s = 0.f;
        for (int i = 0; i < 64; ++i) s += g_part[blockIdx.x][i];
        g_isum[blockIdx.x] = 0.1f / s;
    }
}

// ================= out = x + 0.1 * O/sum (concat over branches) ===================
__global__ __launch_bounds__(256) void final_kernel(const float* __restrict__ x,
                                                    float* __restrict__ out) {
    int idx = blockIdx.x * 256 + threadIdx.x;
    int r = idx >> 9, c = idx & 511;
    int b = c >> 8, cc = c & 255;
    out[idx] = fmaf(g_O[b][r * HID + cc], g_isum[b], x[idx]);
}

// =================================================================================
extern "C" void kernel_launch(void* const* d_in, const int* in_sizes, int n_in,
                              void* d_out, int out_size) {
    const float* x   = (const float*)d_in[0];
    const float* box = (const float*)d_in[1];
    const float* WG1 = (const float*)d_in[2];
    const float* WK1 = (const float*)d_in[3];
    const float* WQ1 = (const float*)d_in[4];
    const float* WV1 = (const float*)d_in[5];
    const float* WG2 = (const float*)d_in[6];
    const float* WK2 = (const float*)d_in[7];
    const float* WQ2 = (const float*)d_in[8];
    const float* WV2 = (const float*)d_in[9];
    float* out = (float*)d_out;

    dim3 pg(4, 64);
    proj_kernel<<<pg, 256>>>(x, WK1, 0, 0);
    proj_kernel<<<pg, 256>>>(x, WQ1, 1, 0);
    proj_kernel<<<pg, 256>>>(x, WV1, 2, 0);
    proj_kernel<<<pg, 256>>>(x, WK2, 0, 1);
    proj_kernel<<<pg, 256>>>(x, WQ2, 1, 1);
    proj_kernel<<<pg, 256>>>(x, WV2, 2, 1);
    gramm_kernel<<<2, 512>>>(WG1, WG2);
    bm_kernel<<<dim3(352, 2), 256>>>(box);
    attn_kernel<<<dim3(64, 2), 256>>>(box);
    sum_kernel<<<2, 32>>>();
    final_kernel<<<8192, 256>>>(x, out);
}